// round 15
// baseline (speedup 1.0000x reference)
#include <cuda_runtime.h>
#include <cuda_fp16.h>

// GaussianMean pull-based. fp16 gather, transposed layout g_uh[node][c2][t].
// 2 warps/node channel-split; block = 4 nodes x 2 warps; meta staged in smem.
// R15: (1) explicit ex2.approx.ftz (MUFU, no polynomial risk);
//      (2) meta padded to multiple of 8 with edges from zero-node N
//          -> uniform unroll-8 loop, no remainder, 8 gathers in flight.
// out[n,t,c] = (sum_e u[from,t,c]*(sw[c]^2*exp(-|x_e-mu_c|^2)+1.01))/max(deg,1)+bias[c]

#define MAX_N 16384
#define CAP   64    // Poisson(16) degree; P(deg>64) ~ 0

__device__ int      g_cnt[MAX_N];          // zero-init; pull self-restores
__device__ float4   g_meta[MAX_N * CAP];   // (x0, x1, |x|^2*log2e, (from*64) bits)
__device__ unsigned g_uh[(MAX_N + 1) * 256]; // half2, node*256 + c2*8 + t; node N stays ZERO

#define L2E 1.4426950408889634f

__device__ __forceinline__ float ex2_approx(float x) {
    float y;
    asm("ex2.approx.ftz.f32 %0, %1;" : "=f"(y) : "f"(x));
    return y;
}

// Fused prep: warp-per-node register transpose, then CSR fill blocks.
__global__ __launch_bounds__(256) void prep_kernel(
    const float2* __restrict__ u2,
    const float2* __restrict__ edge_attr2,
    const int*    __restrict__ efrom,
    const int*    __restrict__ eto,
    int N, int transBlocks, int Ed)
{
    const int tid = threadIdx.x;
    if ((int)blockIdx.x < transBlocks) {
        const int node = blockIdx.x * 8 + (tid >> 5);
        if (node >= N) return;
        const int lane = tid & 31;
        unsigned h[8];
#pragma unroll
        for (int t = 0; t < 8; t++) {
            float2 v = __ldg(&u2[node * 256 + t * 32 + lane]);
            __half2 hh = __floats2half2_rn(v.x, v.y);
            h[t] = *reinterpret_cast<unsigned*>(&hh);
        }
        uint4* dst = reinterpret_cast<uint4*>(g_uh + node * 256 + lane * 8);
        dst[0] = make_uint4(h[0], h[1], h[2], h[3]);
        dst[1] = make_uint4(h[4], h[5], h[6], h[7]);
    } else {
        const int e = (blockIdx.x - transBlocks) * 256 + tid;
        if (e < Ed) {
            int to  = eto[e];
            int pos = atomicAdd(&g_cnt[to], 1);
            if (pos < CAP) {
                float2 x = edge_attr2[e * 6 + 5];   // floats 10,11 of 12-float row
                float x2l = (x.x * x.x + x.y * x.y) * L2E;
                g_meta[to * CAP + pos] =
                    make_float4(x.x, x.y, x2l, __int_as_float(efrom[e] << 6));
            }
        }
    }
}

// Block = 4 nodes x 2 warps (channel halves).
__global__ __launch_bounds__(256) void pull_kernel(
    const float4* __restrict__ mu4,    // mu4[c2] = (mu[2c2], mu[2c2+1])
    const float2* __restrict__ sw2,
    const float2* __restrict__ bias2,
    float2*       __restrict__ out2,
    int N)
{
    __shared__ int    sdeg[4];
    __shared__ float4 smeta[4][CAP];
    const int tid  = threadIdx.x;
    const int w    = tid >> 5;
    const int lane = tid & 31;
    const int nodeBase = blockIdx.x * 4;

    if (tid < 4) {
        int nn = nodeBase + tid;
        sdeg[tid] = (nn < N) ? g_cnt[nn] : 0;
    }
    __syncthreads();
    if (tid < 4) {
        int nn = nodeBase + tid;
        if (nn < N) g_cnt[nn] = 0;              // self-restore; all warps use sdeg
    }
    // stage meta + pad to multiple of 8 with zero-node edges
    if (w < 4) {
        const int nn = nodeBase + w;
        if (nn < N) {
            const int dd   = min(sdeg[w], CAP);
            const int dpad = (dd + 7) & ~7;     // <= CAP
            const float4* mp = g_meta + nn * CAP;
#pragma unroll 2
            for (int j = lane; j < dd; j += 32) smeta[w][j] = __ldg(&mp[j]);
            // padding: from = N (g_uh[N] region is zero -> contributes 0)
            int jp = dd + lane;
            if (jp < dpad)
                smeta[w][jp] = make_float4(0.0f, 0.0f, 0.0f,
                                           __int_as_float(N << 6));
        }
    }
    __syncthreads();

    const int n = nodeBase + (w >> 1);
    if (n >= N) return;
    const int h  = w & 1;                       // channel half
    const int c2 = h * 16 + (lane & 15);        // this lane's channel pair
    const int th = lane >> 4;                   // time half (4 t's)

    const int deg  = sdeg[w >> 1];
    const int dpad = (min(deg, CAP) + 7) & ~7;

    // log2-domain gaussian constants for channels 2c2, 2c2+1
    const float4 mm = __ldg(&mu4[c2]);
    const float2 wt = __ldg(&sw2[c2]);
    const float A0 = 2.0f * mm.x * L2E, B0 = 2.0f * mm.y * L2E;
    const float C0 = -(mm.x * mm.x + mm.y * mm.y) * L2E;
    const float A1 = 2.0f * mm.z * L2E, B1 = 2.0f * mm.w * L2E;
    const float C1 = -(mm.z * mm.z + mm.w * mm.w) * L2E;
    const float s0 = wt.x * wt.x, s1 = wt.y * wt.y;

    __half2 hacc[4];
#pragma unroll
    for (int i = 0; i < 4; i++) hacc[i] = __floats2half2_rn(0.0f, 0.0f);

    const float4* mrow = smeta[w >> 1];
    const uint4* ubp = reinterpret_cast<const uint4*>(g_uh) + (c2 * 2 + th);

#pragma unroll 8
    for (int j = 0; j < dpad; j++) {
        const float4 md = mrow[j];                           // LDS, broadcast
        const uint4  hq = __ldg(&ubp[__float_as_int(md.w)]); // gather 16B/lane

        float t0 = fmaf(A0, md.x, fmaf(B0, md.y, C0 - md.z));
        float t1 = fmaf(A1, md.x, fmaf(B1, md.y, C1 - md.z));
        float w0 = fmaf(s0, ex2_approx(t0), 1.01f);
        float w1 = fmaf(s1, ex2_approx(t1), 1.01f);
        const __half2 wh = __floats2half2_rn(w0, w1);

        const __half2* hp = reinterpret_cast<const __half2*>(&hq);
#pragma unroll
        for (int k = 0; k < 4; k++)
            hacc[k] = __hfma2(hp[k], wh, hacc[k]);
    }

    const float  inv = 1.0f / fmaxf((float)deg, 1.0f);
    const float2 b   = __ldg(&bias2[c2]);
    float2* op = out2 + (size_t)n * 256 + (size_t)th * 128 + c2;
#pragma unroll
    for (int tl = 0; tl < 4; tl++) {
        float2 uf = __half22float2(hacc[tl]);
        float2 v;
        v.x = uf.x * inv + b.x;
        v.y = uf.y * inv + b.y;
        op[tl * 32] = v;
    }
}

extern "C" void kernel_launch(void* const* d_in, const int* in_sizes, int n_in,
                              void* d_out, int out_size)
{
    const float* u_l       = (const float*)d_in[0];
    const float* edge_attr = (const float*)d_in[1];
    const int*   efrom     = (const int*)  d_in[2];
    const int*   eto       = (const int*)  d_in[3];
    const float* mu        = (const float*)d_in[4];
    const float* sw        = (const float*)d_in[5];
    const float* bias      = (const float*)d_in[6];

    const int Ed = in_sizes[2];           // 160000
    const int N  = in_sizes[0] / 512;     // 10000

    const int transBlocks = (N + 7) / 8;
    const int fillBlocks  = (Ed + 255) / 256;
    prep_kernel<<<transBlocks + fillBlocks, 256>>>(
        (const float2*)u_l, (const float2*)edge_attr, efrom, eto, N, transBlocks, Ed);

    // 4 nodes x 2 warps per 256-thread block
    pull_kernel<<<(N + 3) / 4, 256>>>(
        (const float4*)mu, (const float2*)sw, (const float2*)bias,
        (float2*)d_out, N);
}

// round 16
// speedup vs baseline: 1.1223x; 1.1223x over previous
#include <cuda_runtime.h>
#include <cuda_fp16.h>

// GaussianMean pull-based. fp16 gather, transposed layout g_uh[node][c2][t].
// R16: ONE warp per node (HFMA2 makes acc cheap: 8 half2 regs for all 8 t's).
// Lane = channel-pair c2; per edge: LDS meta + 2x LDG.128 + 8 HFMA2.
// Meta staged in smem per 8-node block. No padding (R15 regression reverted).
// out[n,t,c] = (sum_e u[from,t,c]*(sw[c]^2*exp(-|x_e-mu_c|^2)+1.01))/max(deg,1)+bias[c]

#define MAX_N 16384
#define CAP   64    // Poisson(16) degree; P(deg>64) ~ 0

__device__ int      g_cnt[MAX_N];          // zero-init; pull self-restores
__device__ float4   g_meta[MAX_N * CAP];   // (x0, x1, |x|^2*log2e, (from*64) bits)
__device__ unsigned g_uh[MAX_N * 256];     // half2, layout node*256 + c2*8 + t

#define L2E 1.4426950408889634f

__device__ __forceinline__ float ex2_approx(float x) {
    float y;
    asm("ex2.approx.ftz.f32 %0, %1;" : "=f"(y) : "f"(x));
    return y;
}

// Fused prep: warp-per-node register transpose, then CSR fill blocks.
__global__ __launch_bounds__(256) void prep_kernel(
    const float2* __restrict__ u2,
    const float2* __restrict__ edge_attr2,
    const int*    __restrict__ efrom,
    const int*    __restrict__ eto,
    int N, int transBlocks, int Ed)
{
    const int tid = threadIdx.x;
    if ((int)blockIdx.x < transBlocks) {
        const int node = blockIdx.x * 8 + (tid >> 5);
        if (node >= N) return;
        const int lane = tid & 31;
        unsigned h[8];
#pragma unroll
        for (int t = 0; t < 8; t++) {
            float2 v = __ldg(&u2[node * 256 + t * 32 + lane]);
            __half2 hh = __floats2half2_rn(v.x, v.y);
            h[t] = *reinterpret_cast<unsigned*>(&hh);
        }
        uint4* dst = reinterpret_cast<uint4*>(g_uh + node * 256 + lane * 8);
        dst[0] = make_uint4(h[0], h[1], h[2], h[3]);
        dst[1] = make_uint4(h[4], h[5], h[6], h[7]);
    } else {
        const int e = (blockIdx.x - transBlocks) * 256 + tid;
        if (e < Ed) {
            int to  = eto[e];
            int pos = atomicAdd(&g_cnt[to], 1);
            if (pos < CAP) {
                float2 x = edge_attr2[e * 6 + 5];   // floats 10,11 of 12-float row
                float x2l = (x.x * x.x + x.y * x.y) * L2E;
                g_meta[to * CAP + pos] =
                    make_float4(x.x, x.y, x2l, __int_as_float(efrom[e] << 6));
            }
        }
    }
}

// Block = 8 warps = 8 nodes. One warp per node; lane = channel-pair c2.
__global__ __launch_bounds__(256) void pull_kernel(
    const float4* __restrict__ mu4,    // mu4[c2] = (mu[2c2], mu[2c2+1])
    const float2* __restrict__ sw2,
    const float2* __restrict__ bias2,
    float2*       __restrict__ out2,
    int N)
{
    __shared__ int    sdeg[8];
    __shared__ float4 smeta[8][CAP];
    const int tid  = threadIdx.x;
    const int w    = tid >> 5;
    const int lane = tid & 31;
    const int nodeBase = blockIdx.x * 8;
    const int n = nodeBase + w;

    if (tid < 8) {
        int nn = nodeBase + tid;
        sdeg[tid] = (nn < N) ? g_cnt[nn] : 0;
    }
    __syncthreads();
    if (tid < 8) {
        int nn = nodeBase + tid;
        if (nn < N) g_cnt[nn] = 0;              // self-restore; warps use sdeg
    }
    // stage meta: warp w stages its own node
    int d = 0;
    if (n < N) {
        d = min(sdeg[w], CAP);
        const float4* mp = g_meta + n * CAP;
#pragma unroll 2
        for (int j = lane; j < d; j += 32) smeta[w][j] = __ldg(&mp[j]);
    }
    __syncthreads();
    if (n >= N) return;

    const int c2 = lane;

    // log2-domain gaussian constants for channels 2c2, 2c2+1
    const float4 mm = __ldg(&mu4[c2]);
    const float2 wt = __ldg(&sw2[c2]);
    const float A0 = 2.0f * mm.x * L2E, B0 = 2.0f * mm.y * L2E;
    const float C0 = -(mm.x * mm.x + mm.y * mm.y) * L2E;
    const float A1 = 2.0f * mm.z * L2E, B1 = 2.0f * mm.w * L2E;
    const float C1 = -(mm.z * mm.z + mm.w * mm.w) * L2E;
    const float s0 = wt.x * wt.x, s1 = wt.y * wt.y;

    __half2 hacc[8];
#pragma unroll
    for (int i = 0; i < 8; i++) hacc[i] = __floats2half2_rn(0.0f, 0.0f);

    const float4* mrow = smeta[w];
    // lane's two uint4 slots within a node block: indices lane*2, lane*2+1
    const uint4* ubp = reinterpret_cast<const uint4*>(g_uh) + (c2 * 2);

#pragma unroll 4
    for (int j = 0; j < d; j++) {
        const float4 md = mrow[j];                            // LDS, broadcast
        const int fofs  = __float_as_int(md.w);               // from*64
        const uint4 hqA = __ldg(&ubp[fofs]);                  // t=0..3
        const uint4 hqB = __ldg(&ubp[fofs + 1]);              // t=4..7

        float t0 = fmaf(A0, md.x, fmaf(B0, md.y, C0 - md.z));
        float t1 = fmaf(A1, md.x, fmaf(B1, md.y, C1 - md.z));
        float w0 = fmaf(s0, ex2_approx(t0), 1.01f);
        float w1 = fmaf(s1, ex2_approx(t1), 1.01f);
        const __half2 wh = __floats2half2_rn(w0, w1);

        const __half2* hA = reinterpret_cast<const __half2*>(&hqA);
        const __half2* hB = reinterpret_cast<const __half2*>(&hqB);
#pragma unroll
        for (int k = 0; k < 4; k++) {
            hacc[k]     = __hfma2(hA[k], wh, hacc[k]);
            hacc[k + 4] = __hfma2(hB[k], wh, hacc[k + 4]);
        }
    }

    const float  inv = 1.0f / fmaxf((float)sdeg[w], 1.0f);
    const float2 b   = __ldg(&bias2[c2]);
    float2* op = out2 + (size_t)n * 256 + c2;
#pragma unroll
    for (int t = 0; t < 8; t++) {
        float2 uf = __half22float2(hacc[t]);
        float2 v;
        v.x = uf.x * inv + b.x;
        v.y = uf.y * inv + b.y;
        op[t * 32] = v;
    }
}

extern "C" void kernel_launch(void* const* d_in, const int* in_sizes, int n_in,
                              void* d_out, int out_size)
{
    const float* u_l       = (const float*)d_in[0];
    const float* edge_attr = (const float*)d_in[1];
    const int*   efrom     = (const int*)  d_in[2];
    const int*   eto       = (const int*)  d_in[3];
    const float* mu        = (const float*)d_in[4];
    const float* sw        = (const float*)d_in[5];
    const float* bias      = (const float*)d_in[6];

    const int Ed = in_sizes[2];           // 160000
    const int N  = in_sizes[0] / 512;     // 10000

    const int transBlocks = (N + 7) / 8;
    const int fillBlocks  = (Ed + 255) / 256;
    prep_kernel<<<transBlocks + fillBlocks, 256>>>(
        (const float2*)u_l, (const float2*)edge_attr, efrom, eto, N, transBlocks, Ed);

    // 1 warp per node, 8 nodes per 256-thread block
    pull_kernel<<<(N + 7) / 8, 256>>>(
        (const float4*)mu, (const float2*)sw, (const float2*)bias,
        (float2*)d_out, N);
}